// round 16
// baseline (speedup 1.0000x reference)
#include <cuda_runtime.h>
#include <cuda_bf16.h>
#include <math.h>

#define KC 16
#define DD 64
#define TILE_M 128
#define XPAD 72   // bf16 per row (64 + 8 pad) -> 144B rows, conflict-free ldmatrix

// ---- compact triangular W layout (per split) ----
// Row-group nt (rows 8nt..8nt+7) keeps only K-blocks kt <= nt/2 (KTN blocks):
// row stride RS(nt) bytes (padded), group offset G(nt) = prefix of 8*RS.
__host__ __device__ constexpr int RS_f(int nt) {
    return (nt < 2) ? 32 : (nt < 4) ? 80 : (nt < 6) ? 112 : 144;
}
__host__ __device__ constexpr int G_f(int nt) {
    // prefix sums of 8*RS: {0,256,512,1152,1792,2688,3584,4736}
    return (nt == 0) ? 0 : (nt == 1) ? 256 : (nt == 2) ? 512
         : (nt == 3) ? 1152 : (nt == 4) ? 1792 : (nt == 5) ? 2688
         : (nt == 6) ? 3584 : 4736;
}
#define WSPLIT_BYTES 6144      // 5888 used, padded
#define WBUF_BYTES  12288      // hi + lo
#define WB_OFF 0               // double buffer: [0,12288) + [12288,24576)

// ---- smem offsets (bytes) ----
// Staging phase: XH [0,18432), XL [18432,36864) — DEAD after A-frag ldmatrix.
// Steady phase (overlaid): W bufs [0,24576), TS, CS, LOG.
#define XH_OFF 0
#define XL_OFF 18432
#define TS_OFF 24576           // t[16][64] fp32
#define CS_OFF 28672           // c[16]
#define LOG_OFF 28736          // maha[16][132] fp32
#define LOG_STRIDE 132
#define SMEM_TOTAL (LOG_OFF + KC * LOG_STRIDE * 4)   // 37184

// Precomputed per-component data
__device__ float g_t[KC][DD];
__device__ float g_c[KC];
// W = L^{-1} split bf16 hi/lo in compact blocked layout: 12288 B per comp
__device__ __align__(16) __nv_bfloat16 g_Wc[KC][WBUF_BYTES / 2];

// ---------------- helpers ----------------
__device__ __forceinline__ unsigned smem_u32(const void* p) {
    return (unsigned)__cvta_generic_to_shared(p);
}
__device__ __forceinline__ void cp16(unsigned dst, const void* src) {
    asm volatile("cp.async.cg.shared.global [%0], [%1], 16;\n" :: "r"(dst), "l"(src));
}
__device__ __forceinline__ void cp_commit() {
    asm volatile("cp.async.commit_group;\n");
}
template <int N> __device__ __forceinline__ void cp_wait() {
    asm volatile("cp.async.wait_group %0;\n" :: "n"(N));
}
__device__ __forceinline__ void ldmx4(unsigned& r0, unsigned& r1, unsigned& r2,
                                      unsigned& r3, unsigned addr) {
    asm volatile("ldmatrix.sync.aligned.m8n8.x4.shared.b16 {%0,%1,%2,%3}, [%4];"
                 : "=r"(r0), "=r"(r1), "=r"(r2), "=r"(r3) : "r"(addr));
}
__device__ __forceinline__ void ldmx2(unsigned& r0, unsigned& r1, unsigned addr) {
    asm volatile("ldmatrix.sync.aligned.m8n8.x2.shared.b16 {%0,%1}, [%2];"
                 : "=r"(r0), "=r"(r1) : "r"(addr));
}
__device__ __forceinline__ void mma_bf16(float* d, const unsigned* a,
                                         const unsigned* b) {
    asm volatile(
        "mma.sync.aligned.m16n8k16.row.col.f32.bf16.bf16.f32 "
        "{%0,%1,%2,%3}, {%4,%5,%6,%7}, {%8,%9}, {%0,%1,%2,%3};"
        : "+f"(d[0]), "+f"(d[1]), "+f"(d[2]), "+f"(d[3])
        : "r"(a[0]), "r"(a[1]), "r"(a[2]), "r"(a[3]), "r"(b[0]), "r"(b[1]));
}

// ---------------- precompute v4 (proven) + compact bf16-split W ----------
__global__ void __launch_bounds__(64)
gmm_precompute_kernel(const float* __restrict__ pi,
                      const float* __restrict__ mus,
                      const float* __restrict__ covs) {
    __shared__ float colbuf[2][DD];
    __shared__ float rinv[DD];
    __shared__ float Ls[DD][DD + 1];
    __shared__ float Wsm[DD][DD + 1];
    __shared__ float mu_s[DD];
    __shared__ float lg[DD];

    const int k = blockIdx.x;
    const int r = threadIdx.x;  // 0..63 (owns W column r)

    float a[DD];
    {
        const float4* src = (const float4*)(covs + ((size_t)k * DD + r) * DD);
#pragma unroll
        for (int i = 0; i < DD / 4; i++) {
            float4 v = src[i];
            a[4 * i] = v.x; a[4 * i + 1] = v.y;
            a[4 * i + 2] = v.z; a[4 * i + 3] = v.w;
        }
    }
    mu_s[r] = mus[k * DD + r];

    float lrow[DD];
    float d_own = 1.0f;
#pragma unroll
    for (int j = 0; j < DD; j++) {
        colbuf[j & 1][r] = a[j];
        __syncthreads();
        const float dj = colbuf[j & 1][j];
        const float rs = rsqrtf(dj);
        const float invd = rs * rs;
        lrow[j] = a[j] * rs;
        if (r == j) d_own = dj;
        const float s = a[j] * invd;
        if (r > j) {
#pragma unroll
            for (int q = j + 1; q < DD; q++)
                a[q] = fmaf(-s, colbuf[j & 1][q], a[q]);
        }
    }

    rinv[r] = rsqrtf(d_own);
    lg[r] = logf(d_own);
#pragma unroll
    for (int j = 0; j < DD; j++)
        Ls[r][j] = (r >= j) ? lrow[j] : 0.0f;
    __syncthreads();

    // thread r computes W column r
    float w[DD];
#pragma unroll
    for (int i = 0; i < DD; i++)
        w[i] = (i == r) ? rinv[r] : 0.0f;
#pragma unroll
    for (int i = 1; i < DD; i++) {
        float acc = 0.0f;
#pragma unroll
        for (int j = 0; j < i; j++)
            acc = fmaf(Ls[i][j], w[j], acc);
        if (i > r) w[i] = -acc * rinv[i];
    }

    // Emit bf16 hi/lo into compact blocked layout. A compact row in group nt
    // holds only 16*(nt/2+1) columns; columns beyond are exact zeros of the
    // upper triangle and MUST NOT be written (they'd alias other rows).
    {
        char* base = (char*)&g_Wc[k][0];
#pragma unroll
        for (int i = 0; i < DD; i++) {
            const int nt = i >> 3;
            const int kept = 16 * (nt / 2 + 1);
            if (r < kept) {
                float wv = w[i];
                __nv_bfloat16 h = __float2bfloat16_rn(wv);
                __nv_bfloat16 l = __float2bfloat16_rn(wv - __bfloat162float(h));
                const unsigned off = (unsigned)G_f(nt)
                                   + (unsigned)(i & 7) * (unsigned)RS_f(nt)
                                   + (unsigned)r * 2u;
                *(__nv_bfloat16*)(base + off) = h;
                *(__nv_bfloat16*)(base + WSPLIT_BYTES + off) = l;
            }
            Wsm[i][r] = w[i];
        }
    }
    __syncthreads();

    {
        float s = 0.0f;
#pragma unroll
        for (int j = 0; j < DD; j++)
            s = fmaf(Wsm[r][j], mu_s[j], s);
        g_t[k][r] = s;
    }
    if (r == 0) {
        float sl = 0.0f;
#pragma unroll
        for (int i = 0; i < DD; i++) sl += lg[i];
        g_c[k] = logf(pi[k]) - 32.0f * 1.8378770664093453f - 0.5f * sl;
    }
}

// ---------------- main kernel: warp-MMA bf16-split triangular GEMM -------
// 128 threads = 4 warps; tile of 128 points; warp w owns points [32w,32w+32).
// 6 independent HMMA accumulator chains per nt group (2 m-tiles x 3 split
// terms), interleaved in program order so in-order issue never stalls on a
// dependent HMMA before the tensor port is free.
__global__ void __launch_bounds__(128, 4)
gmm_main_kernel(const float* __restrict__ X, float* __restrict__ out, int n) {
    extern __shared__ __align__(16) char smem[];
    const int tid = threadIdx.x;
    const int warp = tid >> 5;
    const int lane = tid & 31;
    const int tile0 = blockIdx.x * TILE_M;

    // ---- stage + split X row tid into padded SMEM (hi/lo) ----
    {
        const int gp = (tile0 + tid < n) ? (tile0 + tid) : (n - 1);
        const float4* xr = (const float4*)(X + (size_t)gp * DD);
        char* xh = smem + XH_OFF + tid * (XPAD * 2);
        char* xl = smem + XL_OFF + tid * (XPAD * 2);
#pragma unroll
        for (int i = 0; i < DD / 4; i++) {
            float4 v = xr[i];
            float vs[4] = {v.x, v.y, v.z, v.w};
#pragma unroll
            for (int h2 = 0; h2 < 2; h2++) {
                float x0 = vs[2 * h2], x1 = vs[2 * h2 + 1];
                __nv_bfloat162 hp, lp;
                hp.x = __float2bfloat16_rn(x0);
                hp.y = __float2bfloat16_rn(x1);
                lp.x = __float2bfloat16_rn(x0 - __bfloat162float(hp.x));
                lp.y = __float2bfloat16_rn(x1 - __bfloat162float(hp.y));
                *(__nv_bfloat162*)(xh + (4 * i + 2 * h2) * 2) = hp;
                *(__nv_bfloat162*)(xl + (4 * i + 2 * h2) * 2) = lp;
            }
        }
        *(float4*)(xh + DD * 2) = make_float4(0.f, 0.f, 0.f, 0.f);
        *(float4*)(xl + DD * 2) = make_float4(0.f, 0.f, 0.f, 0.f);
    }
    __syncthreads();   // X staged

    // ---- load A fragments (X hi/lo) into registers ----
    unsigned Ah[2][4][4], Al[2][4][4];
    {
        const int rbase = 32 * warp + (lane & 7) + ((lane >> 3) & 1) * 8;
        const int cbase = ((lane >> 4) & 1) * 8;
#pragma unroll
        for (int mt = 0; mt < 2; mt++) {
#pragma unroll
            for (int kt = 0; kt < 4; kt++) {
                unsigned off = (unsigned)(rbase + 16 * mt) * (XPAD * 2)
                             + (unsigned)(16 * kt + cbase) * 2;
                unsigned ah = smem_u32(smem + XH_OFF) + off;
                unsigned al = smem_u32(smem + XL_OFF) + off;
                ldmx4(Ah[mt][kt][0], Ah[mt][kt][1], Ah[mt][kt][2], Ah[mt][kt][3], ah);
                ldmx4(Al[mt][kt][0], Al[mt][kt][1], Al[mt][kt][2], Al[mt][kt][3], al);
            }
        }
    }
    __syncthreads();   // ALL warps done reading X -> whole region reusable

    // ---- prefetch W0 into buffer 0 + t/c tables (overlay region) ----
    {
        const float4* src = (const float4*)&g_Wc[0][0];
        unsigned dst = smem_u32(smem + WB_OFF);
#pragma unroll
        for (int i = 0; i < 6; i++)
            cp16(dst + (unsigned)(tid + 128 * i) * 16, src + tid + 128 * i);
        cp_commit();
    }
    for (int idx = tid; idx < KC * DD; idx += 128)
        ((float*)(smem + TS_OFF))[idx] = ((const float*)g_t)[idx];
    if (tid < KC) ((float*)(smem + CS_OFF))[tid] = g_c[tid];

    float* logp = (float*)(smem + LOG_OFF);

#pragma unroll 1
    for (int k = 0; k < KC; k++) {
        const int buf = k & 1;
        cp_wait<0>();
        __syncthreads();   // W k (+ tables on k=0) visible; prev reads done

        if (k < KC - 1) {  // prefetch W k+1 into the other buffer
            const float4* src = (const float4*)&g_Wc[k + 1][0];
            unsigned dst = smem_u32(smem + WB_OFF) + (unsigned)(buf ^ 1) * WBUF_BYTES;
#pragma unroll
            for (int i = 0; i < 6; i++)
                cp16(dst + (unsigned)(tid + 128 * i) * 16, src + tid + 128 * i);
            cp_commit();
        }

        const unsigned wb_hi = smem_u32(smem + WB_OFF) + (unsigned)buf * WBUF_BYTES;
        const unsigned wb_lo = wb_hi + WSPLIT_BYTES;
        const unsigned lrow = (unsigned)(lane & 7);
        const unsigned bcol = (unsigned)(((lane >> 3) & 1) * 8) * 2;
        const float* tk = (const float*)(smem + TS_OFF) + k * DD;

        float sA0 = 0.0f, sB0 = 0.0f, sA1 = 0.0f, sB1 = 0.0f;

#pragma unroll
        for (int nt = 0; nt < 8; nt++) {
            // Triangular W, compact layout: group nt holds kt blocks 0..nt/2.
            const int KTN = nt / 2 + 1;   // compile-time (nt unrolled)
            unsigned bh[4][2], bl[4][2];
#pragma unroll
            for (int kt = 0; kt < KTN; kt++) {
                unsigned off = (unsigned)G_f(nt) + lrow * (unsigned)RS_f(nt)
                             + (unsigned)(kt * 32) + bcol;
                ldmx2(bh[kt][0], bh[kt][1], wb_hi + off);
                ldmx2(bl[kt][0], bl[kt][1], wb_lo + off);
            }
            // 6 independent accumulator chains, interleaved issue order:
            // {mt0,mt1} x {hi*hi, lo*hi, hi*lo}
            float D0h[4] = {0, 0, 0, 0}, D0c[4] = {0, 0, 0, 0},
                  D0d[4] = {0, 0, 0, 0};
            float D1h[4] = {0, 0, 0, 0}, D1c[4] = {0, 0, 0, 0},
                  D1d[4] = {0, 0, 0, 0};
#pragma unroll
            for (int kt = 0; kt < KTN; kt++) {
                mma_bf16(D0h, Ah[0][kt], bh[kt]);
                mma_bf16(D1h, Ah[1][kt], bh[kt]);
                mma_bf16(D0c, Al[0][kt], bh[kt]);
                mma_bf16(D1c, Al[1][kt], bh[kt]);
                mma_bf16(D0d, Ah[0][kt], bl[kt]);
                mma_bf16(D1d, Ah[1][kt], bl[kt]);
            }
            const float2 tv = *(const float2*)(tk + 8 * nt + 2 * (lane & 3));
            {
                float d0 = (D0h[0] + D0c[0] + D0d[0]) - tv.x;
                float d1 = (D0h[1] + D0c[1] + D0d[1]) - tv.y;
                float d2 = (D0h[2] + D0c[2] + D0d[2]) - tv.x;
                float d3 = (D0h[3] + D0c[3] + D0d[3]) - tv.y;
                sA0 = fmaf(d0, d0, fmaf(d1, d1, sA0));
                sB0 = fmaf(d2, d2, fmaf(d3, d3, sB0));
            }
            {
                float d0 = (D1h[0] + D1c[0] + D1d[0]) - tv.x;
                float d1 = (D1h[1] + D1c[1] + D1d[1]) - tv.y;
                float d2 = (D1h[2] + D1c[2] + D1d[2]) - tv.x;
                float d3 = (D1h[3] + D1c[3] + D1d[3]) - tv.y;
                sA1 = fmaf(d0, d0, fmaf(d1, d1, sA1));
                sB1 = fmaf(d2, d2, fmaf(d3, d3, sB1));
            }
        }

        // ---- reduce across lane quads, write logs ----
        sA0 += __shfl_xor_sync(0xffffffffu, sA0, 1);
        sA0 += __shfl_xor_sync(0xffffffffu, sA0, 2);
        sB0 += __shfl_xor_sync(0xffffffffu, sB0, 1);
        sB0 += __shfl_xor_sync(0xffffffffu, sB0, 2);
        sA1 += __shfl_xor_sync(0xffffffffu, sA1, 1);
        sA1 += __shfl_xor_sync(0xffffffffu, sA1, 2);
        sB1 += __shfl_xor_sync(0xffffffffu, sB1, 1);
        sB1 += __shfl_xor_sync(0xffffffffu, sB1, 2);
        if ((lane & 3) == 0) {
            const int row = 32 * warp + (lane >> 2);
            logp[k * LOG_STRIDE + row] = sA0;
            logp[k * LOG_STRIDE + row + 8] = sB0;
            logp[k * LOG_STRIDE + row + 16] = sA1;
            logp[k * LOG_STRIDE + row + 24] = sB1;
        }
    }
    __syncthreads();

    // ---- fused softmax over components ----
    const int p = tile0 + tid;
    if (p < n) {
        const float* csp = (const float*)(smem + CS_OFF);
        float w[KC];
        float m = -INFINITY;
#pragma unroll
        for (int k = 0; k < KC; k++) {
            w[k] = csp[k] - 0.5f * logp[k * LOG_STRIDE + tid];
            m = fmaxf(m, w[k]);
        }
        float s = 0.0f;
#pragma unroll
        for (int k = 0; k < KC; k++) {
            w[k] = __expf(w[k] - m);
            s += w[k];
        }
        const float inv = 1.0f / s;
        float4* orow = (float4*)(out + (size_t)p * KC);
#pragma unroll
        for (int q = 0; q < KC / 4; q++)
            orow[q] = make_float4(w[4 * q] * inv, w[4 * q + 1] * inv,
                                  w[4 * q + 2] * inv, w[4 * q + 3] * inv);
    }
}

extern "C" void kernel_launch(void* const* d_in, const int* in_sizes, int n_in,
                              void* d_out, int out_size) {
    const float* X    = (const float*)d_in[0];  // [N, 64]
    const float* pi   = (const float*)d_in[1];  // [16]
    const float* mus  = (const float*)d_in[2];  // [16, 64]
    const float* covs = (const float*)d_in[3];  // [16, 64, 64]
    float* out = (float*)d_out;                 // [N, 16]

    const int n = in_sizes[0] / DD;

    cudaFuncSetAttribute(gmm_main_kernel,
                         cudaFuncAttributeMaxDynamicSharedMemorySize, SMEM_TOTAL);

    gmm_precompute_kernel<<<KC, DD>>>(pi, mus, covs);
    gmm_main_kernel<<<(n + TILE_M - 1) / TILE_M, 128, SMEM_TOTAL>>>(X, out, n);
}

// round 17
// speedup vs baseline: 1.0105x; 1.0105x over previous
#include <cuda_runtime.h>
#include <cuda_bf16.h>
#include <math.h>

#define KC 16
#define DD 64
#define TILE_M 128
#define XPAD 72   // bf16 per row (64 + 8 pad) -> 144B rows, conflict-free ldmatrix

// ---- compact triangular W layout (per split) ----
__host__ __device__ constexpr int RS_f(int nt) {
    return (nt < 2) ? 32 : (nt < 4) ? 80 : (nt < 6) ? 112 : 144;
}
__host__ __device__ constexpr int G_f(int nt) {
    return (nt == 0) ? 0 : (nt == 1) ? 256 : (nt == 2) ? 512
         : (nt == 3) ? 1152 : (nt == 4) ? 1792 : (nt == 5) ? 2688
         : (nt == 6) ? 3584 : 4736;
}
#define WSPLIT_BYTES 6144      // 5888 used, padded
#define WBUF_BYTES  12288      // hi + lo
#define WB_OFF 0               // double buffer: [0,12288) + [12288,24576)

// ---- smem offsets (bytes) ----
#define XH_OFF 0
#define XL_OFF 18432
#define TS_OFF 24576           // t[16][64] fp32
#define CS_OFF 28672           // c[16]
#define LOG_OFF 28736          // maha[16][132] fp32
#define LOG_STRIDE 132
#define SMEM_TOTAL (LOG_OFF + KC * LOG_STRIDE * 4)   // 37184

// Precomputed per-component data
__device__ float g_t[KC][DD];
__device__ float g_c[KC];
__device__ __align__(16) __nv_bfloat16 g_Wc[KC][WBUF_BYTES / 2];

// ---------------- helpers ----------------
__device__ __forceinline__ unsigned smem_u32(const void* p) {
    return (unsigned)__cvta_generic_to_shared(p);
}
__device__ __forceinline__ void cp16(unsigned dst, const void* src) {
    asm volatile("cp.async.cg.shared.global [%0], [%1], 16;\n" :: "r"(dst), "l"(src));
}
__device__ __forceinline__ void cp_commit() {
    asm volatile("cp.async.commit_group;\n");
}
template <int N> __device__ __forceinline__ void cp_wait() {
    asm volatile("cp.async.wait_group %0;\n" :: "n"(N));
}
__device__ __forceinline__ void ldmx4(unsigned& r0, unsigned& r1, unsigned& r2,
                                      unsigned& r3, unsigned addr) {
    asm volatile("ldmatrix.sync.aligned.m8n8.x4.shared.b16 {%0,%1,%2,%3}, [%4];"
                 : "=r"(r0), "=r"(r1), "=r"(r2), "=r"(r3) : "r"(addr));
}
__device__ __forceinline__ void mma_bf16(float* d, const unsigned* a,
                                         const unsigned* b) {
    asm volatile(
        "mma.sync.aligned.m16n8k16.row.col.f32.bf16.bf16.f32 "
        "{%0,%1,%2,%3}, {%4,%5,%6,%7}, {%8,%9}, {%0,%1,%2,%3};"
        : "+f"(d[0]), "+f"(d[1]), "+f"(d[2]), "+f"(d[3])
        : "r"(a[0]), "r"(a[1]), "r"(a[2]), "r"(a[3]), "r"(b[0]), "r"(b[1]));
}

// ---------------- precompute v4 (proven) + compact bf16-split W ----------
__global__ void __launch_bounds__(64)
gmm_precompute_kernel(const float* __restrict__ pi,
                      const float* __restrict__ mus,
                      const float* __restrict__ covs) {
    __shared__ float colbuf[2][DD];
    __shared__ float rinv[DD];
    __shared__ float Ls[DD][DD + 1];
    __shared__ float Wsm[DD][DD + 1];
    __shared__ float mu_s[DD];
    __shared__ float lg[DD];

    const int k = blockIdx.x;
    const int r = threadIdx.x;  // 0..63 (owns W column r)

    float a[DD];
    {
        const float4* src = (const float4*)(covs + ((size_t)k * DD + r) * DD);
#pragma unroll
        for (int i = 0; i < DD / 4; i++) {
            float4 v = src[i];
            a[4 * i] = v.x; a[4 * i + 1] = v.y;
            a[4 * i + 2] = v.z; a[4 * i + 3] = v.w;
        }
    }
    mu_s[r] = mus[k * DD + r];

    float lrow[DD];
    float d_own = 1.0f;
#pragma unroll
    for (int j = 0; j < DD; j++) {
        colbuf[j & 1][r] = a[j];
        __syncthreads();
        const float dj = colbuf[j & 1][j];
        const float rs = rsqrtf(dj);
        const float invd = rs * rs;
        lrow[j] = a[j] * rs;
        if (r == j) d_own = dj;
        const float s = a[j] * invd;
        if (r > j) {
#pragma unroll
            for (int q = j + 1; q < DD; q++)
                a[q] = fmaf(-s, colbuf[j & 1][q], a[q]);
        }
    }

    rinv[r] = rsqrtf(d_own);
    lg[r] = logf(d_own);
#pragma unroll
    for (int j = 0; j < DD; j++)
        Ls[r][j] = (r >= j) ? lrow[j] : 0.0f;
    __syncthreads();

    float w[DD];
#pragma unroll
    for (int i = 0; i < DD; i++)
        w[i] = (i == r) ? rinv[r] : 0.0f;
#pragma unroll
    for (int i = 1; i < DD; i++) {
        float acc = 0.0f;
#pragma unroll
        for (int j = 0; j < i; j++)
            acc = fmaf(Ls[i][j], w[j], acc);
        if (i > r) w[i] = -acc * rinv[i];
    }

    // Emit bf16 hi/lo into compact blocked layout; only kept columns written.
    {
        char* base = (char*)&g_Wc[k][0];
#pragma unroll
        for (int i = 0; i < DD; i++) {
            const int nt = i >> 3;
            const int kept = 16 * (nt / 2 + 1);
            if (r < kept) {
                float wv = w[i];
                __nv_bfloat16 h = __float2bfloat16_rn(wv);
                __nv_bfloat16 l = __float2bfloat16_rn(wv - __bfloat162float(h));
                const unsigned off = (unsigned)G_f(nt)
                                   + (unsigned)(i & 7) * (unsigned)RS_f(nt)
                                   + (unsigned)r * 2u;
                *(__nv_bfloat16*)(base + off) = h;
                *(__nv_bfloat16*)(base + WSPLIT_BYTES + off) = l;
            }
            Wsm[i][r] = w[i];
        }
    }
    __syncthreads();

    {
        float s = 0.0f;
#pragma unroll
        for (int j = 0; j < DD; j++)
            s = fmaf(Wsm[r][j], mu_s[j], s);
        g_t[k][r] = s;
    }
    if (r == 0) {
        float sl = 0.0f;
#pragma unroll
        for (int i = 0; i < DD; i++) sl += lg[i];
        g_c[k] = logf(pi[k]) - 32.0f * 1.8378770664093453f - 0.5f * sl;
    }
}

// ---------------- main kernel: warp-MMA bf16-split triangular GEMM -------
// Component-phase staggered per CTA (decorrelate co-resident CTA epilogues);
// hi/lo B tiles loaded with one ldmatrix.x4 (lanes 0-15 hi, 16-31 lo).
__global__ void __launch_bounds__(128, 4)
gmm_main_kernel(const float* __restrict__ X, float* __restrict__ out, int n) {
    extern __shared__ __align__(16) char smem[];
    const int tid = threadIdx.x;
    const int warp = tid >> 5;
    const int lane = tid & 31;
    const int tile0 = blockIdx.x * TILE_M;
    const int phase = blockIdx.x & (KC - 1);

    // ---- stage + split X row tid into padded SMEM (hi/lo) ----
    {
        const int gp = (tile0 + tid < n) ? (tile0 + tid) : (n - 1);
        const float4* xr = (const float4*)(X + (size_t)gp * DD);
        char* xh = smem + XH_OFF + tid * (XPAD * 2);
        char* xl = smem + XL_OFF + tid * (XPAD * 2);
#pragma unroll
        for (int i = 0; i < DD / 4; i++) {
            float4 v = xr[i];
            float vs[4] = {v.x, v.y, v.z, v.w};
#pragma unroll
            for (int h2 = 0; h2 < 2; h2++) {
                float x0 = vs[2 * h2], x1 = vs[2 * h2 + 1];
                __nv_bfloat162 hp, lp;
                hp.x = __float2bfloat16_rn(x0);
                hp.y = __float2bfloat16_rn(x1);
                lp.x = __float2bfloat16_rn(x0 - __bfloat162float(hp.x));
                lp.y = __float2bfloat16_rn(x1 - __bfloat162float(hp.y));
                *(__nv_bfloat162*)(xh + (4 * i + 2 * h2) * 2) = hp;
                *(__nv_bfloat162*)(xl + (4 * i + 2 * h2) * 2) = lp;
            }
        }
        *(float4*)(xh + DD * 2) = make_float4(0.f, 0.f, 0.f, 0.f);
        *(float4*)(xl + DD * 2) = make_float4(0.f, 0.f, 0.f, 0.f);
    }
    __syncthreads();   // X staged

    // ---- load A fragments (X hi/lo) into registers ----
    unsigned Ah[2][4][4], Al[2][4][4];
    {
        const int rbase = 32 * warp + (lane & 7) + ((lane >> 3) & 1) * 8;
        const int cbase = ((lane >> 4) & 1) * 8;
#pragma unroll
        for (int mt = 0; mt < 2; mt++) {
#pragma unroll
            for (int kt = 0; kt < 4; kt++) {
                unsigned off = (unsigned)(rbase + 16 * mt) * (XPAD * 2)
                             + (unsigned)(16 * kt + cbase) * 2;
                unsigned ah = smem_u32(smem + XH_OFF) + off;
                unsigned al = smem_u32(smem + XL_OFF) + off;
                ldmx4(Ah[mt][kt][0], Ah[mt][kt][1], Ah[mt][kt][2], Ah[mt][kt][3], ah);
                ldmx4(Al[mt][kt][0], Al[mt][kt][1], Al[mt][kt][2], Al[mt][kt][3], al);
            }
        }
    }
    __syncthreads();   // ALL warps done reading X -> whole region reusable

    // ---- prefetch W[phase] into buffer 0 + t/c tables ----
    {
        const float4* src = (const float4*)&g_Wc[phase][0];
        unsigned dst = smem_u32(smem + WB_OFF);
#pragma unroll
        for (int i = 0; i < 6; i++)
            cp16(dst + (unsigned)(tid + 128 * i) * 16, src + tid + 128 * i);
        cp_commit();
    }
    for (int idx = tid; idx < KC * DD; idx += 128)
        ((float*)(smem + TS_OFF))[idx] = ((const float*)g_t)[idx];
    if (tid < KC) ((float*)(smem + CS_OFF))[tid] = g_c[tid];

    float* logp = (float*)(smem + LOG_OFF);

    // lane-invariant part of the B ldmatrix.x4 address:
    // lanes 0-15 -> hi split, 16-31 -> lo split; within each, row=(lane&7),
    // k-half=((lane>>3)&1)*16 bytes.
    const unsigned lsel = ((unsigned)(lane >> 4) & 1u) * (unsigned)WSPLIT_BYTES
                        + ((unsigned)(lane >> 3) & 1u) * 16u;
    const unsigned lrow = (unsigned)(lane & 7);

#pragma unroll 1
    for (int k = 0; k < KC; k++) {
        const int kp = (k + phase) & (KC - 1);     // this CTA's component
        const int buf = k & 1;
        cp_wait<0>();
        __syncthreads();   // W kp (+ tables on k=0) visible; prev reads done

        if (k < KC - 1) {  // prefetch next component into the other buffer
            const int knext = (kp + 1) & (KC - 1);
            const float4* src = (const float4*)&g_Wc[knext][0];
            unsigned dst = smem_u32(smem + WB_OFF) + (unsigned)(buf ^ 1) * WBUF_BYTES;
#pragma unroll
            for (int i = 0; i < 6; i++)
                cp16(dst + (unsigned)(tid + 128 * i) * 16, src + tid + 128 * i);
            cp_commit();
        }

        const unsigned wb = smem_u32(smem + WB_OFF) + (unsigned)buf * WBUF_BYTES
                          + lsel + lrow * 0u;  // lrow folded per-group below
        const float* tk = (const float*)(smem + TS_OFF) + kp * DD;

        float sA0 = 0.0f, sB0 = 0.0f, sA1 = 0.0f, sB1 = 0.0f;

#pragma unroll
        for (int nt = 0; nt < 8; nt++) {
            const int KTN = nt / 2 + 1;   // compile-time (nt unrolled)
            unsigned bh[4][2], bl[4][2];
            const unsigned gbase = wb + (unsigned)G_f(nt)
                                 + lrow * (unsigned)RS_f(nt);
#pragma unroll
            for (int kt = 0; kt < KTN; kt++) {
                // one x4: {hi k0-7, hi k8-15, lo k0-7, lo k8-15}
                ldmx4(bh[kt][0], bh[kt][1], bl[kt][0], bl[kt][1],
                      gbase + (unsigned)(kt * 32));
            }
            // 6 independent accumulator chains, interleaved issue order
            float D0h[4] = {0, 0, 0, 0}, D0c[4] = {0, 0, 0, 0},
                  D0d[4] = {0, 0, 0, 0};
            float D1h[4] = {0, 0, 0, 0}, D1c[4] = {0, 0, 0, 0},
                  D1d[4] = {0, 0, 0, 0};
#pragma unroll
            for (int kt = 0; kt < KTN; kt++) {
                mma_bf16(D0h, Ah[0][kt], bh[kt]);
                mma_bf16(D1h, Ah[1][kt], bh[kt]);
                mma_bf16(D0c, Al[0][kt], bh[kt]);
                mma_bf16(D1c, Al[1][kt], bh[kt]);
                mma_bf16(D0d, Ah[0][kt], bl[kt]);
                mma_bf16(D1d, Ah[1][kt], bl[kt]);
            }
            const float2 tv = *(const float2*)(tk + 8 * nt + 2 * (lane & 3));
            {
                float d0 = (D0h[0] + D0c[0] + D0d[0]) - tv.x;
                float d1 = (D0h[1] + D0c[1] + D0d[1]) - tv.y;
                float d2 = (D0h[2] + D0c[2] + D0d[2]) - tv.x;
                float d3 = (D0h[3] + D0c[3] + D0d[3]) - tv.y;
                sA0 = fmaf(d0, d0, fmaf(d1, d1, sA0));
                sB0 = fmaf(d2, d2, fmaf(d3, d3, sB0));
            }
            {
                float d0 = (D1h[0] + D1c[0] + D1d[0]) - tv.x;
                float d1 = (D1h[1] + D1c[1] + D1d[1]) - tv.y;
                float d2 = (D1h[2] + D1c[2] + D1d[2]) - tv.x;
                float d3 = (D1h[3] + D1c[3] + D1d[3]) - tv.y;
                sA1 = fmaf(d0, d0, fmaf(d1, d1, sA1));
                sB1 = fmaf(d2, d2, fmaf(d3, d3, sB1));
            }
        }

        // ---- reduce across lane quads, write logs (row = component kp) ----
        sA0 += __shfl_xor_sync(0xffffffffu, sA0, 1);
        sA0 += __shfl_xor_sync(0xffffffffu, sA0, 2);
        sB0 += __shfl_xor_sync(0xffffffffu, sB0, 1);
        sB0 += __shfl_xor_sync(0xffffffffu, sB0, 2);
        sA1 += __shfl_xor_sync(0xffffffffu, sA1, 1);
        sA1 += __shfl_xor_sync(0xffffffffu, sA1, 2);
        sB1 += __shfl_xor_sync(0xffffffffu, sB1, 1);
        sB1 += __shfl_xor_sync(0xffffffffu, sB1, 2);
        if ((lane & 3) == 0) {
            const int row = 32 * warp + (lane >> 2);
            logp[kp * LOG_STRIDE + row] = sA0;
            logp[kp * LOG_STRIDE + row + 8] = sB0;
            logp[kp * LOG_STRIDE + row + 16] = sA1;
            logp[kp * LOG_STRIDE + row + 24] = sB1;
        }
    }
    __syncthreads();

    // ---- fused softmax over components ----
    const int p = tile0 + tid;
    if (p < n) {
        const float* csp = (const float*)(smem + CS_OFF);
        float w[KC];
        float m = -INFINITY;
#pragma unroll
        for (int k = 0; k < KC; k++) {
            w[k] = csp[k] - 0.5f * logp[k * LOG_STRIDE + tid];
            m = fmaxf(m, w[k]);
        }
        float s = 0.0f;
#pragma unroll
        for (int k = 0; k < KC; k++) {
            w[k] = __expf(w[k] - m);
            s += w[k];
        }
        const float inv = 1.0f / s;
        float4* orow = (float4*)(out + (size_t)p * KC);
#pragma unroll
        for (int q = 0; q < KC / 4; q++)
            orow[q] = make_float4(w[4 * q] * inv, w[4 * q + 1] * inv,
                                  w[4 * q + 2] * inv, w[4 * q + 3] * inv);
    }
}

extern "C" void kernel_launch(void* const* d_in, const int* in_sizes, int n_in,
                              void* d_out, int out_size) {
    const float* X    = (const float*)d_in[0];  // [N, 64]
    const float* pi   = (const float*)d_in[1];  // [16]
    const float* mus  = (const float*)d_in[2];  // [16, 64]
    const float* covs = (const float*)d_in[3];  // [16, 64, 64]
    float* out = (float*)d_out;                 // [N, 16]

    const int n = in_sizes[0] / DD;

    cudaFuncSetAttribute(gmm_main_kernel,
                         cudaFuncAttributeMaxDynamicSharedMemorySize, SMEM_TOTAL);

    gmm_precompute_kernel<<<KC, DD>>>(pi, mus, covs);
    gmm_main_kernel<<<(n + TILE_M - 1) / TILE_M, 128, SMEM_TOTAL>>>(X, out, n);
}